// round 5
// baseline (speedup 1.0000x reference)
#include <cuda_runtime.h>
#include <math.h>

// Problem constants
#define NB    32
#define HH    192
#define CC    64
#define EPS   1e-5f
#define PADX  65       // xs row stride in floats (odd -> conflict-free fill stores)

// Scratch (device globals — allocation-free)
__device__ __align__(16) float g_S[NB * 64 * 64 * CC];       // 3x3 sub-block sums
__device__ __align__(16) float g_tok[2 * NB * 32 * 32 * CC]; // tokens [p][b][i][j][c]

typedef unsigned long long u64;

__device__ __forceinline__ float gelu_exact(float v) {
    return 0.5f * v * (1.0f + erff(v * 0.7071067811865476f));
}
__device__ __forceinline__ u64 pk2(float lo, float hi) {
    u64 r; asm("mov.b64 %0, {%1, %2};" : "=l"(r) : "f"(lo), "f"(hi)); return r;
}
__device__ __forceinline__ void upk2(float& lo, float& hi, u64 v) {
    asm("mov.b64 {%0, %1}, %2;" : "=f"(lo), "=f"(hi) : "l"(v));
}
__device__ __forceinline__ u64 ffma2(u64 a, u64 b, u64 c) {
    u64 d; asm("fma.rn.f32x2 %0, %1, %2, %3;" : "=l"(d) : "l"(a), "l"(b), "l"(c)); return d;
}

// ---------------------------------------------------------------------------
// K1: 3x3 sub-block sums (85% DRAM roofline — leave alone).
// ---------------------------------------------------------------------------
__global__ void __launch_bounds__(256) k1_subsum(const float* __restrict__ x) {
    int tid = blockIdx.x * blockDim.x + threadIdx.x;
    int c4 = tid & 15;
    int sw = (tid >> 4) & 63;
    int sh = (tid >> 10) & 63;
    int b  = tid >> 16;
    const float4* x4 = (const float4*)x;
    float4 acc = make_float4(0.f, 0.f, 0.f, 0.f);
    int rowbase = (b * HH + sh * 3) * HH + sw * 3;
#pragma unroll
    for (int dh = 0; dh < 3; dh++)
#pragma unroll
        for (int dw = 0; dw < 3; dw++) {
            float4 v = x4[(rowbase + dh * HH + dw) * 16 + c4];
            acc.x += v.x; acc.y += v.y; acc.z += v.z; acc.w += v.w;
        }
    ((float4*)g_S)[tid] = acc;
}

// ---------------------------------------------------------------------------
// GEMM(64x64 @ 64x64) + LayerNorm + GELU, 64-row tile.
// 256 threads: ctx = tid&7 owns channels {4ctx..4ctx+3, 4ctx+32..4ctx+35};
// cty = tid>>3 owns tokens {2cty, 2cty+1}. 16 f32x2 accumulators.
// Per k: 2 conflict-free LDS.128 (weights, 4-way bcast), 2 LDS.32 (tokens,
// 8-way bcast), 8 fma.rn.f32x2.
// ---------------------------------------------------------------------------
__device__ __forceinline__ void gemm_ln_gelu(
    const float* Ws, const float* xs,
    const float* __restrict__ bias, const float* __restrict__ gam,
    const float* __restrict__ bet,
    int ctx, int cty, float y[2][8])
{
    int c0 = ctx * 4;
    float2 bl0 = *(const float2*)(bias + c0);
    float2 bl1 = *(const float2*)(bias + c0 + 2);
    float2 bh0 = *(const float2*)(bias + c0 + 32);
    float2 bh1 = *(const float2*)(bias + c0 + 34);
    u64 acc[2][4];
    acc[0][0] = pk2(bl0.x, bl0.y); acc[0][1] = pk2(bl1.x, bl1.y);
    acc[0][2] = pk2(bh0.x, bh0.y); acc[0][3] = pk2(bh1.x, bh1.y);
#pragma unroll
    for (int p = 0; p < 4; p++) acc[1][p] = acc[0][p];
    const float* xrow = xs + cty * 2;
#pragma unroll 8
    for (int k = 0; k < 64; k++) {
        ulonglong2 wl = *(const ulonglong2*)(Ws + k * 64 + c0);
        ulonglong2 wh = *(const ulonglong2*)(Ws + k * 64 + c0 + 32);
        float xa = xrow[k * PADX];
        float xb = xrow[k * PADX + 1];
        u64 x0 = pk2(xa, xa), x1 = pk2(xb, xb);
        acc[0][0] = ffma2(x0, wl.x, acc[0][0]); acc[0][1] = ffma2(x0, wl.y, acc[0][1]);
        acc[0][2] = ffma2(x0, wh.x, acc[0][2]); acc[0][3] = ffma2(x0, wh.y, acc[0][3]);
        acc[1][0] = ffma2(x1, wl.x, acc[1][0]); acc[1][1] = ffma2(x1, wl.y, acc[1][1]);
        acc[1][2] = ffma2(x1, wh.x, acc[1][2]); acc[1][3] = ffma2(x1, wh.y, acc[1][3]);
    }
    float4 gl = *(const float4*)(gam + c0);
    float4 gh = *(const float4*)(gam + c0 + 32);
    float4 el = *(const float4*)(bet + c0);
    float4 eh = *(const float4*)(bet + c0 + 32);
    float ga[8] = {gl.x, gl.y, gl.z, gl.w, gh.x, gh.y, gh.z, gh.w};
    float be[8] = {el.x, el.y, el.z, el.w, eh.x, eh.y, eh.z, eh.w};
#pragma unroll
    for (int t = 0; t < 2; t++) {
        float v[8];
        upk2(v[0], v[1], acc[t][0]); upk2(v[2], v[3], acc[t][1]);
        upk2(v[4], v[5], acc[t][2]); upk2(v[6], v[7], acc[t][3]);
        float s = 0.f;
#pragma unroll
        for (int j = 0; j < 8; j++) s += v[j];
        s += __shfl_xor_sync(0xffffffffu, s, 1);
        s += __shfl_xor_sync(0xffffffffu, s, 2);
        s += __shfl_xor_sync(0xffffffffu, s, 4);
        float mean = s * (1.0f / 64.0f);
        float var = 0.f;
#pragma unroll
        for (int j = 0; j < 8; j++) { float d = v[j] - mean; var += d * d; }
        var += __shfl_xor_sync(0xffffffffu, var, 1);
        var += __shfl_xor_sync(0xffffffffu, var, 2);
        var += __shfl_xor_sync(0xffffffffu, var, 4);
        float rstd = rsqrtf(var * (1.0f / 64.0f) + EPS);
#pragma unroll
        for (int j = 0; j < 8; j++) {
            float yn = (v[j] - mean) * rstd * ga[j] + be[j];
            y[t][j] = gelu_exact(yn);
        }
    }
}

// ---------------------------------------------------------------------------
// K2: token projection, both paths. 64 token rows per CTA (1024 CTAs).
// ---------------------------------------------------------------------------
__global__ void __launch_bounds__(256, 3) k2_token(
    const float* __restrict__ tW, const float* __restrict__ tb,
    const float* __restrict__ tg, const float* __restrict__ tbe)
{
    __shared__ float Ws[4096];
    __shared__ float xs[64 * PADX];
    int tid = threadIdx.x;
    for (int i = tid; i < 4096; i += 256) Ws[i] = tW[i];
    int R0 = blockIdx.x * 64;
#pragma unroll 4
    for (int e = 0; e < 16; e++) {
        int idx = e * 256 + tid;
        int t = idx >> 6, c = idx & 63;
        int R = R0 + t;
        int p = R >> 15, rem = R & 32767;
        int bb = rem >> 10, ii = (rem >> 5) & 31, jj = rem & 31;
        int r0, r1, q0, q1;
        if (p == 0) { r0 = 2 * ii;            r1 = 2 * ii + 1;
                      q0 = 2 * jj;            q1 = 2 * jj + 1; }
        else        { r0 = (2 * ii + 1) & 63; r1 = (2 * ii + 2) & 63;
                      q0 = (2 * jj + 1) & 63; q1 = (2 * jj + 2) & 63; }
        const float* Sb = g_S + bb * (64 * 64 * CC);
        float s = Sb[(r0 * 64 + q0) * 64 + c] + Sb[(r0 * 64 + q1) * 64 + c]
                + Sb[(r1 * 64 + q0) * 64 + c] + Sb[(r1 * 64 + q1) * 64 + c];
        xs[c * PADX + t] = s * (1.0f / 36.0f);
    }
    __syncthreads();
    int ctx = tid & 7, cty = tid >> 3;
    float y[2][8];
    gemm_ln_gelu(Ws, xs, tb, tg, tbe, ctx, cty, y);
#pragma unroll
    for (int t = 0; t < 2; t++) {
        int R = R0 + cty * 2 + t;
        ((float4*)g_tok)[R * 16 + ctx]     = make_float4(y[t][0], y[t][1], y[t][2], y[t][3]);
        ((float4*)g_tok)[R * 16 + ctx + 8] = make_float4(y[t][4], y[t][5], y[t][6], y[t][7]);
    }
}

// ---------------------------------------------------------------------------
// K3: fuse block + out block per unique 3x3 block, broadcast to 9 pixels.
// 64 rows per CTA (2048 CTAs).
// ---------------------------------------------------------------------------
__global__ void __launch_bounds__(256, 3) k3_fuse_out(
    const float* __restrict__ fW, const float* __restrict__ fb,
    const float* __restrict__ fg, const float* __restrict__ fbe,
    const float* __restrict__ oW, const float* __restrict__ ob,
    const float* __restrict__ og, const float* __restrict__ obe,
    float* __restrict__ out)
{
    __shared__ float Ws[4096];
    __shared__ float xs[64 * PADX];
    int tid = threadIdx.x;
    for (int i = tid; i < 4096; i += 256) Ws[i] = fW[i];
    int R0 = blockIdx.x * 64;
#pragma unroll 4
    for (int e = 0; e < 16; e++) {
        int idx = e * 256 + tid;
        int t = idx >> 6, c = idx & 63;
        int R = R0 + t;
        int bb = R >> 12, qh = (R >> 6) & 63, qw = R & 63;
        int ih = qh >> 1, iw = qw >> 1;
        int sh = ((qh + 63) & 63) >> 1, sw = ((qw + 63) & 63) >> 1;
        float xv = g_tok[((bb * 32 + ih) * 32 + iw) * 64 + c]
                 + g_tok[2097152 + ((bb * 32 + sh) * 32 + sw) * 64 + c];
        xs[c * PADX + t] = xv;
    }
    __syncthreads();
    int ctx = tid & 7, cty = tid >> 3;
    float y[2][8];
    gemm_ln_gelu(Ws, xs, fb, fg, fbe, ctx, cty, y);      // fuse block
    __syncthreads();                                      // all xs/Ws reads done
    // write layer-1 activations back; swap weights to out_W
#pragma unroll
    for (int t = 0; t < 2; t++)
#pragma unroll
        for (int j = 0; j < 8; j++) {
            int c = ctx * 4 + (j < 4 ? j : 28 + j);
            xs[c * PADX + cty * 2 + t] = y[t][j];
        }
    for (int i = tid; i < 4096; i += 256) Ws[i] = oW[i];
    __syncthreads();
    gemm_ln_gelu(Ws, xs, ob, og, obe, ctx, cty, y);      // out block
    // broadcast each unique row to its 3x3 pixel block
    float4* o4 = (float4*)out;
#pragma unroll
    for (int t = 0; t < 2; t++) {
        int R = R0 + cty * 2 + t;
        int bb = R >> 12, qh = (R >> 6) & 63, qw = R & 63;
        float4 vlo = make_float4(y[t][0], y[t][1], y[t][2], y[t][3]);
        float4 vhi = make_float4(y[t][4], y[t][5], y[t][6], y[t][7]);
        int base = (bb * 36864 + qh * 3 * HH + qw * 3) * 16;
#pragma unroll
        for (int dh = 0; dh < 3; dh++)
#pragma unroll
            for (int dw = 0; dw < 3; dw++) {
                int pix = base + (dh * HH + dw) * 16;
                o4[pix + ctx]     = vlo;
                o4[pix + ctx + 8] = vhi;
            }
    }
}

// ---------------------------------------------------------------------------
extern "C" void kernel_launch(void* const* d_in, const int* in_sizes, int n_in,
                              void* d_out, int out_size) {
    const float* h_pixel = (const float*)d_in[0];
    const float* tW  = (const float*)d_in[1];
    const float* tb  = (const float*)d_in[2];
    const float* tg  = (const float*)d_in[3];
    const float* tbe = (const float*)d_in[4];
    const float* fW  = (const float*)d_in[5];
    const float* fb  = (const float*)d_in[6];
    const float* fg  = (const float*)d_in[7];
    const float* fbe = (const float*)d_in[8];
    const float* oW  = (const float*)d_in[9];
    const float* ob  = (const float*)d_in[10];
    const float* og  = (const float*)d_in[11];
    const float* obe = (const float*)d_in[12];
    float* out = (float*)d_out;

    k1_subsum<<<8192, 256>>>(h_pixel);
    k2_token<<<1024, 256>>>(tW, tb, tg, tbe);
    k3_fuse_out<<<2048, 256>>>(fW, fb, fg, fbe, oW, ob, og, obe, out);
}

// round 7
// speedup vs baseline: 1.3322x; 1.3322x over previous
#include <cuda_runtime.h>
#include <math.h>
#include <stdint.h>

#define EPS  1e-5f
#define HHH  192
#define XSTR 68          // xs row stride (words): A-fragment LDS conflict-free
#define WSTR 72          // w row stride (words): B-fragment LDS conflict-free
#define CPO  0           // params: up to 6 x 64 floats
#define XSO  384         // xs: 128 x XSTR
#define WHIO (XSO + 128 * XSTR)          // 9088
#define WLOO (WHIO + 64 * WSTR)          // 13696
#define SMF  (WLOO + 64 * WSTR)          // 18304 floats
#define SMB  (SMF * 4)                   // 73216 bytes

// Scratch (device globals — allocation-free)
__device__ __align__(16) float g_S[32 * 64 * 64 * 64];        // 3x3 sub-block sums
__device__ __align__(16) float g_tok[2 * 32 * 32 * 32 * 64];  // tokens [p][b][i][j][c]

__device__ __forceinline__ float tf32r(float x) {
    uint32_t u; asm("cvt.rna.tf32.f32 %0, %1;" : "=r"(u) : "f"(x));
    return __uint_as_float(u);
}
__device__ __forceinline__ void mma8(float* d, const uint32_t* a, uint32_t b0, uint32_t b1) {
    asm volatile(
        "mma.sync.aligned.m16n8k8.row.col.f32.tf32.tf32.f32 "
        "{%0,%1,%2,%3}, {%4,%5,%6,%7}, {%8,%9}, {%0,%1,%2,%3};"
        : "+f"(d[0]), "+f"(d[1]), "+f"(d[2]), "+f"(d[3])
        : "r"(a[0]), "r"(a[1]), "r"(a[2]), "r"(a[3]), "r"(b0), "r"(b1));
}
__device__ __forceinline__ float gelu_exact(float v) {
    return 0.5f * v * (1.0f + erff(v * 0.7071067811865476f));
}

// ---------------------------------------------------------------------------
// K1: 3x3 sub-block sums (85% of DRAM roofline — unchanged).
// ---------------------------------------------------------------------------
__global__ void __launch_bounds__(256) k1_subsum(const float* __restrict__ x) {
    int tid = blockIdx.x * blockDim.x + threadIdx.x;
    int c4 = tid & 15;
    int sw = (tid >> 4) & 63;
    int sh = (tid >> 10) & 63;
    int b  = tid >> 16;
    const float4* x4 = (const float4*)x;
    float4 acc = make_float4(0.f, 0.f, 0.f, 0.f);
    int rowbase = (b * HHH + sh * 3) * HHH + sw * 3;
#pragma unroll
    for (int dh = 0; dh < 3; dh++)
#pragma unroll
        for (int dw = 0; dw < 3; dw++) {
            float4 v = x4[(rowbase + dh * HHH + dw) * 16 + c4];
            acc.x += v.x; acc.y += v.y; acc.z += v.z; acc.w += v.w;
        }
    ((float4*)g_S)[tid] = acc;
}

// load 64x64 W[k][n] -> tf32 hi/lo split tiles (stride WSTR)
__device__ __forceinline__ void load_wsplit(const float* __restrict__ W, float* sm, int tid) {
    float* whi = sm + WHIO;
    float* wlo = sm + WLOO;
#pragma unroll
    for (int e = 0; e < 4; e++) {
        int idx = e * 256 + tid;
        int k = idx >> 4, n4 = idx & 15;
        float4 wv = ((const float4*)W)[idx];
        int base = k * WSTR + 4 * n4;
        float h;
        h = tf32r(wv.x); whi[base]     = h; wlo[base]     = tf32r(wv.x - h);
        h = tf32r(wv.y); whi[base + 1] = h; wlo[base + 1] = tf32r(wv.y - h);
        h = tf32r(wv.z); whi[base + 2] = h; wlo[base + 2] = tf32r(wv.z - h);
        h = tf32r(wv.w); whi[base + 3] = h; wlo[base + 3] = tf32r(wv.w - h);
    }
}

// GEMM(128x64 @ 64x64) via mma.sync tf32 3-pass split, + bias + LN + GELU.
// Warp w owns rows [16w,16w+16); outputs in v[2][16]: v[0]=row 16w+g,
// v[1]=row 16w+g+8; cols {8j+2q, 8j+2q+1}.
__device__ __forceinline__ void gemm_ln_gelu(float* sm, const float* cp, int tid,
                                             float v[2][16]) {
    int w = tid >> 5, lane = tid & 31, g = lane >> 2, q = lane & 3;
    const float* xs  = sm + XSO;
    const float* whi = sm + WHIO;
    const float* wlo = sm + WLOO;
    float acc[8][4];
#pragma unroll
    for (int j = 0; j < 8; j++) {
        float2 b2 = *(const float2*)(cp + 8 * j + 2 * q);
        acc[j][0] = b2.x; acc[j][1] = b2.y; acc[j][2] = b2.x; acc[j][3] = b2.y;
    }
    int r0 = 16 * w + g;
#pragma unroll
    for (int ks = 0; ks < 8; ks++) {
        int k0 = ks * 8 + q;
        float x0 = xs[r0 * XSTR + k0];
        float x1 = xs[(r0 + 8) * XSTR + k0];
        float x2 = xs[r0 * XSTR + k0 + 4];
        float x3 = xs[(r0 + 8) * XSTR + k0 + 4];
        float h0 = tf32r(x0), h1 = tf32r(x1), h2 = tf32r(x2), h3 = tf32r(x3);
        uint32_t Ahi[4] = { __float_as_uint(h0), __float_as_uint(h1),
                            __float_as_uint(h2), __float_as_uint(h3) };
        uint32_t Alo[4] = { __float_as_uint(tf32r(x0 - h0)), __float_as_uint(tf32r(x1 - h1)),
                            __float_as_uint(tf32r(x2 - h2)), __float_as_uint(tf32r(x3 - h3)) };
#pragma unroll
        for (int j = 0; j < 8; j++) {
            int nn = 8 * j + g;
            uint32_t bh0 = __float_as_uint(whi[k0 * WSTR + nn]);
            uint32_t bh1 = __float_as_uint(whi[(k0 + 4) * WSTR + nn]);
            uint32_t bl0 = __float_as_uint(wlo[k0 * WSTR + nn]);
            uint32_t bl1 = __float_as_uint(wlo[(k0 + 4) * WSTR + nn]);
            mma8(acc[j], Ahi, bh0, bh1);
            mma8(acc[j], Ahi, bl0, bl1);
            mma8(acc[j], Alo, bh0, bh1);
        }
    }
#pragma unroll
    for (int j = 0; j < 8; j++) {
        v[0][2 * j] = acc[j][0]; v[0][2 * j + 1] = acc[j][1];
        v[1][2 * j] = acc[j][2]; v[1][2 * j + 1] = acc[j][3];
    }
#pragma unroll
    for (int t = 0; t < 2; t++) {
        float s = 0.f;
#pragma unroll
        for (int i = 0; i < 16; i++) s += v[t][i];
        s += __shfl_xor_sync(0xffffffffu, s, 1);
        s += __shfl_xor_sync(0xffffffffu, s, 2);
        float mean = s * (1.0f / 64.0f);
        float var = 0.f;
#pragma unroll
        for (int i = 0; i < 16; i++) { float d = v[t][i] - mean; var += d * d; }
        var += __shfl_xor_sync(0xffffffffu, var, 1);
        var += __shfl_xor_sync(0xffffffffu, var, 2);
        float rstd = rsqrtf(var * (1.0f / 64.0f) + EPS);
#pragma unroll
        for (int j = 0; j < 8; j++) {
            float2 gm = *(const float2*)(cp + 64  + 8 * j + 2 * q);
            float2 bt = *(const float2*)(cp + 128 + 8 * j + 2 * q);
            v[t][2 * j]     = gelu_exact((v[t][2 * j]     - mean) * rstd * gm.x + bt.x);
            v[t][2 * j + 1] = gelu_exact((v[t][2 * j + 1] - mean) * rstd * gm.y + bt.y);
        }
    }
}

// ---------------------------------------------------------------------------
// K2: token projection (both paths). 128 rows/CTA, 512 CTAs.
// ---------------------------------------------------------------------------
__global__ void __launch_bounds__(256) k2_token(
    const float* __restrict__ tW, const float* __restrict__ tb,
    const float* __restrict__ tg, const float* __restrict__ tbe)
{
    extern __shared__ __align__(16) float sm[];
    int tid = threadIdx.x;
    if (tid < 64) {
        sm[CPO + tid] = tb[tid]; sm[CPO + 64 + tid] = tg[tid]; sm[CPO + 128 + tid] = tbe[tid];
    }
    load_wsplit(tW, sm, tid);
    float* xs = sm + XSO;
    int R0 = blockIdx.x * 128;
#pragma unroll 2
    for (int e = 0; e < 8; e++) {
        int idx = e * 256 + tid;
        int r = idx >> 4, c4 = idx & 15;
        int R = R0 + r;
        int p = R >> 15, rem = R & 32767;
        int bb = rem >> 10, ii = (rem >> 5) & 31, jj = rem & 31;
        int r0, r1, q0, q1;
        if (p == 0) { r0 = 2 * ii;            r1 = 2 * ii + 1;
                      q0 = 2 * jj;            q1 = 2 * jj + 1; }
        else        { r0 = (2 * ii + 1) & 63; r1 = (2 * ii + 2) & 63;
                      q0 = (2 * jj + 1) & 63; q1 = (2 * jj + 2) & 63; }
        const float4* Sb = (const float4*)g_S + bb * 65536;
        float4 s0 = Sb[(r0 * 64 + q0) * 16 + c4];
        float4 s1 = Sb[(r0 * 64 + q1) * 16 + c4];
        float4 s2 = Sb[(r1 * 64 + q0) * 16 + c4];
        float4 s3 = Sb[(r1 * 64 + q1) * 16 + c4];
        *(float4*)(xs + r * XSTR + 4 * c4) =
            make_float4((s0.x + s1.x + s2.x + s3.x) * (1.0f / 36.0f),
                        (s0.y + s1.y + s2.y + s3.y) * (1.0f / 36.0f),
                        (s0.z + s1.z + s2.z + s3.z) * (1.0f / 36.0f),
                        (s0.w + s1.w + s2.w + s3.w) * (1.0f / 36.0f));
    }
    __syncthreads();
    float v[2][16];
    gemm_ln_gelu(sm, sm + CPO, tid, v);
    int w = tid >> 5, lane = tid & 31, g = lane >> 2, q = lane & 3;
    int R = R0 + 16 * w + g;
#pragma unroll
    for (int j = 0; j < 8; j++) {
        *(float2*)&g_tok[R * 64 + 8 * j + 2 * q]       = make_float2(v[0][2*j], v[0][2*j+1]);
        *(float2*)&g_tok[(R + 8) * 64 + 8 * j + 2 * q] = make_float2(v[1][2*j], v[1][2*j+1]);
    }
}

// ---------------------------------------------------------------------------
// K3: fuse + out layers per unique 3x3 block (128 rows/CTA, 1024 CTAs),
// broadcast each row to its 9 output pixels.
// ---------------------------------------------------------------------------
__global__ void __launch_bounds__(256) k3_fuse_out(
    const float* __restrict__ fW, const float* __restrict__ fb,
    const float* __restrict__ fg, const float* __restrict__ fbe,
    const float* __restrict__ oW, const float* __restrict__ ob,
    const float* __restrict__ og, const float* __restrict__ obe,
    float* __restrict__ out)
{
    extern __shared__ __align__(16) float sm[];
    int tid = threadIdx.x;
    if (tid < 64) {
        sm[CPO + tid]       = fb[tid]; sm[CPO + 64 + tid]  = fg[tid]; sm[CPO + 128 + tid] = fbe[tid];
        sm[CPO + 192 + tid] = ob[tid]; sm[CPO + 256 + tid] = og[tid]; sm[CPO + 320 + tid] = obe[tid];
    }
    load_wsplit(fW, sm, tid);
    float* xs = sm + XSO;
    int R0 = blockIdx.x * 128;
#pragma unroll 2
    for (int e = 0; e < 8; e++) {
        int idx = e * 256 + tid;
        int r = idx >> 4, c4 = idx & 15;
        int R = R0 + r;
        int bb = R >> 12, qh = (R >> 6) & 63, qw = R & 63;
        int ih = qh >> 1, iw = qw >> 1;
        int sh = ((qh + 63) & 63) >> 1, sw_ = ((qw + 63) & 63) >> 1;
        float4 a = ((const float4*)g_tok)[((bb * 32 + ih) * 32 + iw) * 16 + c4];
        float4 s = ((const float4*)g_tok)[524288 + ((bb * 32 + sh) * 32 + sw_) * 16 + c4];
        *(float4*)(xs + r * XSTR + 4 * c4) =
            make_float4(a.x + s.x, a.y + s.y, a.z + s.z, a.w + s.w);
    }
    __syncthreads();
    int w = tid >> 5, lane = tid & 31, g = lane >> 2, q = lane & 3;
    int r0 = 16 * w + g;
    float v[2][16];
    // ---- layer 1: fuse ----
    gemm_ln_gelu(sm, sm + CPO, tid, v);
    __syncthreads();                      // all reads of xs/W done
#pragma unroll
    for (int j = 0; j < 8; j++) {
        *(float2*)&xs[r0 * XSTR + 8 * j + 2 * q]       = make_float2(v[0][2*j], v[0][2*j+1]);
        *(float2*)&xs[(r0 + 8) * XSTR + 8 * j + 2 * q] = make_float2(v[1][2*j], v[1][2*j+1]);
    }
    load_wsplit(oW, sm, tid);
    __syncthreads();
    // ---- layer 2: out ----
    gemm_ln_gelu(sm, sm + CPO + 192, tid, v);
    __syncthreads();                      // all reads of xs done
#pragma unroll
    for (int j = 0; j < 8; j++) {
        *(float2*)&xs[r0 * XSTR + 8 * j + 2 * q]       = make_float2(v[0][2*j], v[0][2*j+1]);
        *(float2*)&xs[(r0 + 8) * XSTR + 8 * j + 2 * q] = make_float2(v[1][2*j], v[1][2*j+1]);
    }
    __syncthreads();
    // coalesced 3x3 broadcast
    float4* o4 = (float4*)out;
#pragma unroll 2
    for (int e = 0; e < 8; e++) {
        int idx = e * 256 + tid;
        int r = idx >> 4, c4 = idx & 15;
        float4 val = *(float4*)(xs + r * XSTR + 4 * c4);
        int R = R0 + r;
        int bb = R >> 12, qh = (R >> 6) & 63, qw = R & 63;
        int base = (bb * 36864 + qh * 3 * HHH + qw * 3) * 16 + c4;
#pragma unroll
        for (int dh = 0; dh < 3; dh++)
#pragma unroll
            for (int dw = 0; dw < 3; dw++)
                o4[base + (dh * HHH + dw) * 16] = val;
    }
}

// ---------------------------------------------------------------------------
extern "C" void kernel_launch(void* const* d_in, const int* in_sizes, int n_in,
                              void* d_out, int out_size) {
    const float* h_pixel = (const float*)d_in[0];
    const float* tW  = (const float*)d_in[1];
    const float* tb  = (const float*)d_in[2];
    const float* tg  = (const float*)d_in[3];
    const float* tbe = (const float*)d_in[4];
    const float* fW  = (const float*)d_in[5];
    const float* fb  = (const float*)d_in[6];
    const float* fg  = (const float*)d_in[7];
    const float* fbe = (const float*)d_in[8];
    const float* oW  = (const float*)d_in[9];
    const float* ob  = (const float*)d_in[10];
    const float* og  = (const float*)d_in[11];
    const float* obe = (const float*)d_in[12];
    float* out = (float*)d_out;

    cudaFuncSetAttribute(k2_token,    cudaFuncAttributeMaxDynamicSharedMemorySize, SMB);
    cudaFuncSetAttribute(k3_fuse_out, cudaFuncAttributeMaxDynamicSharedMemorySize, SMB);

    k1_subsum<<<8192, 256>>>(h_pixel);
    k2_token<<<512, 256, SMB>>>(tW, tb, tg, tbe);
    k3_fuse_out<<<1024, 256, SMB>>>(fW, fb, fg, fbe, oW, ob, og, obe, out);
}